// round 9
// baseline (speedup 1.0000x reference)
#include <cuda_runtime.h>
#include <cuda_fp16.h>
#include <cstdint>

// ============================ helpers ============================
__device__ __forceinline__ uint32_t smem_u32(const void* p) {
    uint32_t a;
    asm("{ .reg .u64 t; cvta.to.shared.u64 t, %1; cvt.u32.u64 %0, t; }" : "=r"(a) : "l"(p));
    return a;
}
#define LDSM_X4(r0, r1, r2, r3, addr) \
    asm volatile("ldmatrix.sync.aligned.m8n8.x4.shared.b16 {%0,%1,%2,%3}, [%4];" \
                 : "=r"(r0), "=r"(r1), "=r"(r2), "=r"(r3) : "r"(addr))
#define MMA_F16(d, a0, a1, a2, a3, b0, b1) \
    asm volatile("mma.sync.aligned.m16n8k16.row.col.f32.f16.f16.f32 " \
                 "{%0,%1,%2,%3},{%4,%5,%6,%7},{%8,%9},{%0,%1,%2,%3};" \
                 : "+f"(d[0]), "+f"(d[1]), "+f"(d[2]), "+f"(d[3]) \
                 : "r"(a0), "r"(a1), "r"(a2), "r"(a3), "r"(b0), "r"(b1))

__device__ __forceinline__ uint32_t pack_half2(__half a, __half b) {
    __half2 h = __halves2half2(a, b);
    return *(uint32_t*)&h;
}

// ============================ scratch ============================
#define MAXN 100000
__device__ float g_deg[MAXN];
__device__ float g_xa[(size_t)MAXN * 128];
__device__ float g_h1[(size_t)MAXN * 256];
__device__ float g_t [(size_t)MAXN * 128];
__device__ float g_h2[(size_t)MAXN * 128];
__device__ float g_z [(size_t)MAXN * 128];
__device__ float g_bnsum[256];
__device__ float g_bnsumsq[256];
__device__ float g_bnsc[256];
__device__ float g_bnsh[256];
// pre-split transposed weights: [NOUT][K] hi/lo halves, K-major rows
__device__ __half g_w1t_hi[256 * 128];
__device__ __half g_w1t_lo[256 * 128];
__device__ __half g_w2t_hi[128 * 256];
__device__ __half g_w2t_lo[128 * 256];
__device__ __half g_w3t_hi[128 * 128];
__device__ __half g_w3t_lo[128 * 128];

// ============================ small kernels ============================
__global__ void deg_kernel(float* __restrict__ deg, const int* __restrict__ dst, int E) {
    int i = blockIdx.x * blockDim.x + threadIdx.x;
    if (i < E) atomicAdd(&deg[dst[i]], 1.0f);
}
__global__ void dinv_kernel(float* __restrict__ deg, int N) {
    int i = blockIdx.x * blockDim.x + threadIdx.x;
    if (i < N) deg[i] = rsqrtf(deg[i] + 1.0f);
}
__global__ void wsplit_kernel(const float* __restrict__ W, __half* __restrict__ hiT,
                              __half* __restrict__ loT, int K, int NOUT) {
    int i = blockIdx.x * blockDim.x + threadIdx.x;
    if (i >= K * NOUT) return;
    int k = i / NOUT, n = i % NOUT;
    float x = W[i];
    __half h = __float2half_rn(x);
    __half l = __float2half_rn(x - __half2float(h));
    hiT[(size_t)n * K + k] = h;
    loT[(size_t)n * K + k] = l;
}
__global__ void agg_kernel(const float* __restrict__ feat, float* __restrict__ out,
                           const int* __restrict__ src, const int* __restrict__ dst, int E,
                           const float* __restrict__ dinv) {
    int w = (blockIdx.x * blockDim.x + threadIdx.x) >> 5;
    int lane = threadIdx.x & 31;
    if (w >= E) return;
    int s = src[w];
    int d = dst[w];
    float coef = dinv[s] * dinv[d];
    float4 v = *(const float4*)(feat + (size_t)s * 128 + lane * 4);
    v.x *= coef; v.y *= coef; v.z *= coef; v.w *= coef;
    float* p = out + (size_t)d * 128 + lane * 4;
    asm volatile("red.global.add.v4.f32 [%0], {%1,%2,%3,%4};"
                 :: "l"(p), "f"(v.x), "f"(v.y), "f"(v.z), "f"(v.w) : "memory");
}
__global__ void selfloop_kernel(const float* __restrict__ x, const float* __restrict__ dinv,
                                float* __restrict__ xa, int N) {
    int i = blockIdx.x * blockDim.x + threadIdx.x;
    if (i >= N * 32) return;
    int row = i >> 5, l = i & 31;
    float di = dinv[row];
    float c = di * di;
    size_t base = (size_t)row * 128 + l * 4;
    float4 v = *(const float4*)(x + base);
    float4 a = *(const float4*)(xa + base);
    a.x += v.x * c; a.y += v.y * c; a.z += v.z * c; a.w += v.w * c;
    *(float4*)(xa + base) = a;
}
__global__ void colstats_kernel(const float* __restrict__ h, float* __restrict__ sum,
                                float* __restrict__ sumsq, int N) {
    int c = threadIdx.x;
    int r0 = blockIdx.x * 256;
    int r1 = min(r0 + 256, N);
    float s = 0.f, s2 = 0.f;
    for (int r = r0; r < r1; r++) {
        float v = h[(size_t)r * 256 + c];
        s += v;
        s2 = fmaf(v, v, s2);
    }
    atomicAdd(&sum[c], s);
    atomicAdd(&sumsq[c], s2);
}
__global__ void bnfinal_kernel(const float* __restrict__ sum, const float* __restrict__ sumsq,
                               const float* __restrict__ gamma, const float* __restrict__ beta,
                               float* __restrict__ sc, float* __restrict__ sh, int N) {
    int c = threadIdx.x;
    float invN = 1.0f / (float)N;
    float mu = sum[c] * invN;
    float var = fmaxf(sumsq[c] * invN - mu * mu, 0.f);
    float scv = gamma[c] * rsqrtf(var + 1e-5f);
    sc[c] = scv;
    sh[c] = beta[c] - mu * scv;
}
__global__ void ln_kernel(const float* __restrict__ agg, const float* __restrict__ t,
                          const float* __restrict__ dinv, const float* __restrict__ b2,
                          const float* __restrict__ lng, const float* __restrict__ lnb,
                          float* __restrict__ out, int N) {
    int w = (blockIdx.x * blockDim.x + threadIdx.x) >> 5;
    int lane = threadIdx.x & 31;
    if (w >= N) return;
    float di = dinv[w];
    float c = di * di;
    size_t base = (size_t)w * 128 + lane * 4;
    float4 a = *(const float4*)(agg + base);
    float4 tv = *(const float4*)(t + base);
    float4 bb = *(const float4*)(b2 + lane * 4);
    float4 v;
    v.x = fmaf(tv.x, c, a.x) + bb.x;
    v.y = fmaf(tv.y, c, a.y) + bb.y;
    v.z = fmaf(tv.z, c, a.z) + bb.z;
    v.w = fmaf(tv.w, c, a.w) + bb.w;
    float s = v.x + v.y + v.z + v.w;
    #pragma unroll
    for (int off = 16; off; off >>= 1) s += __shfl_xor_sync(0xffffffffu, s, off);
    float mu = s * (1.0f / 128.0f);
    float dx = v.x - mu, dy = v.y - mu, dz = v.z - mu, dw = v.w - mu;
    float q = dx * dx + dy * dy + dz * dz + dw * dw;
    #pragma unroll
    for (int off = 16; off; off >>= 1) q += __shfl_xor_sync(0xffffffffu, q, off);
    float rs = rsqrtf(q * (1.0f / 128.0f) + 1e-5f);
    float4 g = *(const float4*)(lng + lane * 4);
    float4 bo = *(const float4*)(lnb + lane * 4);
    float4 o;
    o.x = fmaxf(fmaf(dx * rs, g.x, bo.x), 0.f);
    o.y = fmaxf(fmaf(dy * rs, g.y, bo.y), 0.f);
    o.z = fmaxf(fmaf(dz * rs, g.z, bo.z), 0.f);
    o.w = fmaxf(fmaf(dw * rs, g.w, bo.w), 0.f);
    *(float4*)(out + base) = o;
}
__global__ void decode_kernel(const float* __restrict__ z, const int* __restrict__ ia,
                              const int* __restrict__ ib,
                              const float* __restrict__ cutoff, float* __restrict__ out,
                              int EL, int writeRound) {
    int w = (blockIdx.x * blockDim.x + threadIdx.x) >> 5;
    int lane = threadIdx.x & 31;
    if (w >= EL) return;
    int a = ia[w];
    int b = ib[w];
    float4 za = *(const float4*)(z + (size_t)a * 128 + lane * 4);
    float4 zb = *(const float4*)(z + (size_t)b * 128 + lane * 4);
    float s = za.x * zb.x + za.y * zb.y + za.z * zb.z + za.w * zb.w;
    #pragma unroll
    for (int off = 16; off; off >>= 1) s += __shfl_xor_sync(0xffffffffu, s, off);
    if (lane == 0) {
        out[w] = s;
        if (writeRound) out[(size_t)EL + w] = (s < cutoff[0]) ? 0.0f : 1.0f;
    }
}

// ============================ mma.sync fp16x3 GEMM ============================
// C[128 x 128 tile] = op(A)[Nrows,K] @ BT^T, BT pre-split hi/lo halves [NOUT][K].
// FUSE: a' = relu(a*sc[k]+sh[k]).  8 warps 2(M)x4(N), warp tile 64x32,
// mma.m16n8k16 f16 with fp32 acc, 3-term hi/lo split (error ~2^-22).
template<int K, bool FUSE, bool HASBIAS>
__global__ void __launch_bounds__(256, 2)
mm_gemm_kernel(const float* __restrict__ A,
               const __half* __restrict__ BTh, const __half* __restrict__ BTl,
               const float* __restrict__ bias,
               const float* __restrict__ sc, const float* __restrict__ sh,
               float* __restrict__ C, int Nrows, int ldC) {
    constexpr int NC   = K / 32;        // k-chunks of 32
    constexpr int PADH = 40;            // halves per padded row (80 B stride)
    constexpr int ASZ  = 128 * PADH * 2;  // bytes per copy (10240)

    extern __shared__ char smem[];
    __half* sAh = (__half*)(smem);
    __half* sAl = (__half*)(smem + ASZ);
    __half* sBh = (__half*)(smem + 2 * ASZ);
    __half* sBl = (__half*)(smem + 3 * ASZ);

    int tid = threadIdx.x, lane = tid & 31, warp = tid >> 5;
    int warpM = warp & 1, warpN = warp >> 1;
    int rowBase  = blockIdx.x * 128;
    int colBaseG = blockIdx.y * 128;

    float acc[4][4][4];
    #pragma unroll
    for (int i = 0; i < 4; i++)
        #pragma unroll
        for (int j = 0; j < 4; j++)
            #pragma unroll
            for (int r = 0; r < 4; r++) acc[i][j][r] = 0.f;

    // loaders: each thread owns (row = tid/2, k-half = (tid&1)*16)
    int larow  = tid >> 1;
    int lkhalf = (tid & 1) * 16;
    bool rOK = (rowBase + larow) < Nrows;
    const float*  aRow  = A   + (size_t)(rowBase + larow) * K + lkhalf;
    const __half* bRowH = BTh + (size_t)(colBaseG + larow) * K + lkhalf;
    const __half* bRowL = BTl + (size_t)(colBaseG + larow) * K + lkhalf;
    __half* sAhp = sAh + larow * PADH + lkhalf;
    __half* sAlp = sAl + larow * PADH + lkhalf;
    __half* sBhp = sBh + larow * PADH + lkhalf;
    __half* sBlp = sBl + larow * PADH + lkhalf;

    // ldmatrix per-lane addresses (byte stride per row = PADH*2 = 80)
    // A x4 groups: [r0-7,k0-7][r8-15,k0-7][r0-7,k8-15][r8-15,k8-15]
    int a_r = (lane & 7) + (lane & 8);
    int a_k = (lane & 16) >> 1;                 // +8 halves if lane>=16
    uint32_t aHbase = smem_u32(sAh) + (uint32_t)(((warpM * 64 + a_r) * PADH + a_k) * 2);
    uint32_t aLbase = aHbase + ASZ;
    // B x4 groups: [n0-7,k0-7][n0-7,k8-15][n8-15,k0-7][n8-15,k8-15]
    int b_n = (lane & 7) + ((lane & 16) >> 1);
    int b_k = lane & 8;                         // +8 halves if bit3
    uint32_t bHbase = smem_u32(sBh) + (uint32_t)(((warpN * 32 + b_n) * PADH + b_k) * 2);
    uint32_t bLbase = bHbase + ASZ;

    for (int c = 0; c < NC; c++) {
        int k0 = c * 32;
        __syncthreads();   // previous chunk's mma reads done
        // ---- A: load 16 floats, fuse, split hi/lo halves, store 2x16B each
        {
            const float4* ap = (const float4*)(aRow + k0);
            uint32_t hw[8], lw[8];
            #pragma unroll
            for (int j = 0; j < 4; j++) {
                float4 v = rOK ? ap[j] : make_float4(0.f, 0.f, 0.f, 0.f);
                if (FUSE) {
                    int kg = k0 + lkhalf + j * 4;
                    float4 s4 = *(const float4*)(sc + kg);
                    float4 h4 = *(const float4*)(sh + kg);
                    v.x = fmaxf(fmaf(v.x, s4.x, h4.x), 0.f);
                    v.y = fmaxf(fmaf(v.y, s4.y, h4.y), 0.f);
                    v.z = fmaxf(fmaf(v.z, s4.z, h4.z), 0.f);
                    v.w = fmaxf(fmaf(v.w, s4.w, h4.w), 0.f);
                }
                __half hx = __float2half_rn(v.x), hy = __float2half_rn(v.y);
                __half hz = __float2half_rn(v.z), hh = __float2half_rn(v.w);
                __half lx = __float2half_rn(v.x - __half2float(hx));
                __half ly = __float2half_rn(v.y - __half2float(hy));
                __half lz = __float2half_rn(v.z - __half2float(hz));
                __half lh = __float2half_rn(v.w - __half2float(hh));
                hw[j * 2]     = pack_half2(hx, hy);
                hw[j * 2 + 1] = pack_half2(hz, hh);
                lw[j * 2]     = pack_half2(lx, ly);
                lw[j * 2 + 1] = pack_half2(lz, lh);
            }
            *(uint4*)(sAhp)     = make_uint4(hw[0], hw[1], hw[2], hw[3]);
            *(uint4*)(sAhp + 8) = make_uint4(hw[4], hw[5], hw[6], hw[7]);
            *(uint4*)(sAlp)     = make_uint4(lw[0], lw[1], lw[2], lw[3]);
            *(uint4*)(sAlp + 8) = make_uint4(lw[4], lw[5], lw[6], lw[7]);
        }
        // ---- B: straight copies of pre-split half weights (16 halves = 2x16B)
        {
            const uint4* bh = (const uint4*)(bRowH + k0);
            const uint4* bl = (const uint4*)(bRowL + k0);
            uint4 h0 = bh[0], h1 = bh[1], l0 = bl[0], l1 = bl[1];
            *(uint4*)(sBhp)     = h0;
            *(uint4*)(sBhp + 8) = h1;
            *(uint4*)(sBlp)     = l0;
            *(uint4*)(sBlp + 8) = l1;
        }
        __syncthreads();

        // ---- compute: 2 k16 steps per chunk
        #pragma unroll
        for (int s = 0; s < 2; s++) {
            uint32_t koff = (uint32_t)(s * 16 * 2);   // bytes
            uint32_t bh[2][4], bl[2][4];
            #pragma unroll
            for (int p = 0; p < 2; p++) {
                uint32_t po = (uint32_t)(p * 16 * PADH * 2);
                LDSM_X4(bh[p][0], bh[p][1], bh[p][2], bh[p][3], bHbase + po + koff);
                LDSM_X4(bl[p][0], bl[p][1], bl[p][2], bl[p][3], bLbase + po + koff);
            }
            #pragma unroll
            for (int i = 0; i < 4; i++) {
                uint32_t io = (uint32_t)(i * 16 * PADH * 2);
                uint32_t ah0, ah1, ah2, ah3, al0, al1, al2, al3;
                LDSM_X4(ah0, ah1, ah2, ah3, aHbase + io + koff);
                LDSM_X4(al0, al1, al2, al3, aLbase + io + koff);
                #pragma unroll
                for (int j = 0; j < 4; j++) {
                    int p = j >> 1, o = (j & 1) * 2;
                    MMA_F16(acc[i][j], ah0, ah1, ah2, ah3, bh[p][o], bh[p][o + 1]);
                    MMA_F16(acc[i][j], ah0, ah1, ah2, ah3, bl[p][o], bl[p][o + 1]);
                    MMA_F16(acc[i][j], al0, al1, al2, al3, bh[p][o], bh[p][o + 1]);
                }
            }
        }
    }

    // ---- epilogue (c frag: lane/4 = row-in-8, (lane&3)*2 = col pair)
    int gid = lane >> 2, tc2 = (lane & 3) * 2;
    #pragma unroll
    for (int i = 0; i < 4; i++) {
        int r0 = rowBase + warpM * 64 + i * 16 + gid;
        int r1 = r0 + 8;
        #pragma unroll
        for (int j = 0; j < 4; j++) {
            int col = colBaseG + warpN * 32 + j * 8 + tc2;
            float bx = 0.f, by = 0.f;
            if (HASBIAS) { bx = bias[col]; by = bias[col + 1]; }
            if (r0 < Nrows) {
                float2 v = make_float2(acc[i][j][0] + bx, acc[i][j][1] + by);
                *(float2*)(C + (size_t)r0 * ldC + col) = v;
            }
            if (r1 < Nrows) {
                float2 v = make_float2(acc[i][j][2] + bx, acc[i][j][3] + by);
                *(float2*)(C + (size_t)r1 * ldC + col) = v;
            }
        }
    }
}

// ============================ launch ============================
extern "C" void kernel_launch(void* const* d_in, const int* in_sizes, int n_in,
                              void* d_out, int out_size) {
    const float* x    = (const float*)d_in[0];
    const int*   ei   = (const int*)d_in[1];
    const int*   eli  = (const int*)d_in[2];
    const float* cut  = (const float*)d_in[3];
    const float* W1   = (const float*)d_in[4];
    const float* b1   = (const float*)d_in[5];
    const float* bng  = (const float*)d_in[6];
    const float* bnb  = (const float*)d_in[7];
    const float* W2   = (const float*)d_in[8];
    const float* b2   = (const float*)d_in[9];
    const float* lng  = (const float*)d_in[10];
    const float* lnb  = (const float*)d_in[11];
    const float* linW = (const float*)d_in[12];
    const float* linb = (const float*)d_in[13];

    int N  = in_sizes[0] / 128;
    int E  = in_sizes[1] / 2;
    int EL = in_sizes[2] / 2;
    const int* src = ei;
    const int* dst = ei + E;
    const int* la  = eli;
    const int* lb  = eli + EL;
    float* out = (float*)d_out;

    void* p;
    float *deg, *xa, *h1, *t, *h2, *z, *bsum, *bsq, *bsc, *bsh;
    __half *w1h, *w1l, *w2h, *w2l, *w3h, *w3l;
    cudaGetSymbolAddress(&p, g_deg);     deg  = (float*)p;
    cudaGetSymbolAddress(&p, g_xa);      xa   = (float*)p;
    cudaGetSymbolAddress(&p, g_h1);      h1   = (float*)p;
    cudaGetSymbolAddress(&p, g_t);       t    = (float*)p;
    cudaGetSymbolAddress(&p, g_h2);      h2   = (float*)p;
    cudaGetSymbolAddress(&p, g_z);       z    = (float*)p;
    cudaGetSymbolAddress(&p, g_bnsum);   bsum = (float*)p;
    cudaGetSymbolAddress(&p, g_bnsumsq); bsq  = (float*)p;
    cudaGetSymbolAddress(&p, g_bnsc);    bsc  = (float*)p;
    cudaGetSymbolAddress(&p, g_bnsh);    bsh  = (float*)p;
    cudaGetSymbolAddress(&p, g_w1t_hi);  w1h  = (__half*)p;
    cudaGetSymbolAddress(&p, g_w1t_lo);  w1l  = (__half*)p;
    cudaGetSymbolAddress(&p, g_w2t_hi);  w2h  = (__half*)p;
    cudaGetSymbolAddress(&p, g_w2t_lo);  w2l  = (__half*)p;
    cudaGetSymbolAddress(&p, g_w3t_hi);  w3h  = (__half*)p;
    cudaGetSymbolAddress(&p, g_w3t_lo);  w3l  = (__half*)p;

    constexpr int SMEMSZ = 4 * 128 * 40 * 2;  // 40960 B
    cudaFuncSetAttribute(mm_gemm_kernel<128, false, true>,
                         cudaFuncAttributeMaxDynamicSharedMemorySize, SMEMSZ);
    cudaFuncSetAttribute(mm_gemm_kernel<256, true, false>,
                         cudaFuncAttributeMaxDynamicSharedMemorySize, SMEMSZ);

    cudaMemsetAsync(deg, 0, (size_t)N * sizeof(float));
    cudaMemsetAsync(xa,  0, (size_t)N * 128 * sizeof(float));
    cudaMemsetAsync(h2,  0, (size_t)N * 128 * sizeof(float));
    cudaMemsetAsync(bsum, 0, 256 * sizeof(float));
    cudaMemsetAsync(bsq,  0, 256 * sizeof(float));

    // pre-split weights (tiny)
    wsplit_kernel<<<(128 * 256 + 255) / 256, 256>>>(W1, w1h, w1l, 128, 256);
    wsplit_kernel<<<(256 * 128 + 255) / 256, 256>>>(W2, w2h, w2l, 256, 128);
    wsplit_kernel<<<(128 * 128 + 255) / 256, 256>>>(linW, w3h, w3l, 128, 128);

    // degree + dinv
    deg_kernel<<<(E + 255) / 256, 256>>>(deg, dst, E);
    dinv_kernel<<<(N + 255) / 256, 256>>>(deg, N);

    int tiles = (N + 127) / 128;

    // layer 1: aggregate x, then GEMM1 (+b1), NOUT=256 via 2 column tiles
    agg_kernel<<<(E + 7) / 8, 256>>>(x, xa, src, dst, E, deg);
    selfloop_kernel<<<((size_t)N * 32 + 255) / 256, 256>>>(x, deg, xa, N);
    mm_gemm_kernel<128, false, true><<<dim3(tiles, 2), 256, SMEMSZ>>>(
        xa, w1h, w1l, b1, nullptr, nullptr, h1, N, 256);

    // BatchNorm stats
    colstats_kernel<<<(N + 255) / 256, 256>>>(h1, bsum, bsq, N);
    bnfinal_kernel<<<1, 256>>>(bsum, bsq, bng, bnb, bsc, bsh, N);

    // layer 2: GEMM2 with fused BN+ReLU on A, then aggregate
    mm_gemm_kernel<256, true, false><<<dim3(tiles, 1), 256, SMEMSZ>>>(
        h1, w2h, w2l, nullptr, bsc, bsh, t, N, 128);
    agg_kernel<<<(E + 7) / 8, 256>>>(t, h2, src, dst, E, deg);

    // self-loop + bias + LayerNorm + ReLU -> xa
    ln_kernel<<<((size_t)N * 32 + 255) / 256, 256>>>(h2, t, deg, b2, lng, lnb, xa, N);

    // final linear (+linb)
    mm_gemm_kernel<128, false, true><<<dim3(tiles, 1), 256, SMEMSZ>>>(
        xa, w3h, w3l, linb, nullptr, nullptr, z, N, 128);

    // decode
    int writeRound = (out_size >= 2 * EL) ? 1 : 0;
    decode_kernel<<<((size_t)EL + 7) / 8, 256>>>(z, la, lb, cut, out, EL, writeRound);
}

// round 11
// speedup vs baseline: 1.1398x; 1.1398x over previous
#include <cuda_runtime.h>
#include <cuda_fp16.h>
#include <cstdint>

// ============================ helpers ============================
__device__ __forceinline__ float tf32rnd(float x) {
    uint32_t o; asm("cvt.rna.tf32.f32 %0, %1;" : "=r"(o) : "f"(x)); return __uint_as_float(o);
}
__device__ __forceinline__ uint32_t smem_u32(const void* p) {
    uint32_t a;
    asm("{ .reg .u64 t; cvta.to.shared.u64 t, %1; cvt.u32.u64 %0, t; }" : "=r"(a) : "l"(p));
    return a;
}
#define LDSM_X4(r0, r1, r2, r3, addr) \
    asm volatile("ldmatrix.sync.aligned.m8n8.x4.shared.b16 {%0,%1,%2,%3}, [%4];" \
                 : "=r"(r0), "=r"(r1), "=r"(r2), "=r"(r3) : "r"(addr))
#define MMA_TF32(d, a0, a1, a2, a3, b0, b1) \
    asm volatile("mma.sync.aligned.m16n8k8.row.col.f32.tf32.tf32.f32 " \
                 "{%0,%1,%2,%3},{%4,%5,%6,%7},{%8,%9},{%0,%1,%2,%3};" \
                 : "+f"(d[0]), "+f"(d[1]), "+f"(d[2]), "+f"(d[3]) \
                 : "r"(a0), "r"(a1), "r"(a2), "r"(a3), "r"(b0), "r"(b1))
#define CP_ASYNC16(dst, src) \
    asm volatile("cp.async.cg.shared.global [%0], [%1], 16;" :: "r"(dst), "l"(src))
#define CP_COMMIT() asm volatile("cp.async.commit_group;")
#define CP_WAIT(n)  asm volatile("cp.async.wait_group %0;" :: "n"(n))

// ============================ scratch ============================
#define MAXN 100000
__device__ float g_deg[MAXN];
__device__ float g_xa[(size_t)MAXN * 128];
__device__ float g_h1[(size_t)MAXN * 256];
__device__ float g_t [(size_t)MAXN * 128];
__device__ float g_h2[(size_t)MAXN * 128];
__device__ float g_z [(size_t)MAXN * 128];
__device__ float g_bnsum[256];
__device__ float g_bnsumsq[256];
__device__ float g_bnsc[256];
__device__ float g_bnsh[256];
// pre-split transposed weights: [NOUT][K] hi/lo fp32, K-major rows
__device__ float g_w1t_hi[256 * 128];
__device__ float g_w1t_lo[256 * 128];
__device__ float g_w2t_hi[128 * 256];
__device__ float g_w2t_lo[128 * 256];
__device__ float g_w3t_hi[128 * 128];
__device__ float g_w3t_lo[128 * 128];

// ============================ small kernels ============================
__global__ void deg_kernel(float* __restrict__ deg, const int* __restrict__ dst, int E) {
    int i = blockIdx.x * blockDim.x + threadIdx.x;
    if (i < E) atomicAdd(&deg[dst[i]], 1.0f);
}
__global__ void dinv_kernel(float* __restrict__ deg, int N) {
    int i = blockIdx.x * blockDim.x + threadIdx.x;
    if (i < N) deg[i] = rsqrtf(deg[i] + 1.0f);
}
__global__ void wsplit_kernel(const float* __restrict__ W, float* __restrict__ hiT,
                              float* __restrict__ loT, int K, int NOUT) {
    int i = blockIdx.x * blockDim.x + threadIdx.x;
    if (i >= K * NOUT) return;
    int k = i / NOUT, n = i % NOUT;
    float x = W[i];
    float h = tf32rnd(x);
    float l = tf32rnd(x - h);
    hiT[(size_t)n * K + k] = h;
    loT[(size_t)n * K + k] = l;
}
__global__ void agg_kernel(const float* __restrict__ feat, float* __restrict__ out,
                           const int* __restrict__ src, const int* __restrict__ dst, int E,
                           const float* __restrict__ dinv) {
    int w = (blockIdx.x * blockDim.x + threadIdx.x) >> 5;
    int lane = threadIdx.x & 31;
    if (w >= E) return;
    int s = src[w];
    int d = dst[w];
    float coef = dinv[s] * dinv[d];
    float4 v = *(const float4*)(feat + (size_t)s * 128 + lane * 4);
    v.x *= coef; v.y *= coef; v.z *= coef; v.w *= coef;
    float* p = out + (size_t)d * 128 + lane * 4;
    asm volatile("red.global.add.v4.f32 [%0], {%1,%2,%3,%4};"
                 :: "l"(p), "f"(v.x), "f"(v.y), "f"(v.z), "f"(v.w) : "memory");
}
__global__ void selfloop_kernel(const float* __restrict__ x, const float* __restrict__ dinv,
                                float* __restrict__ xa, int N) {
    int i = blockIdx.x * blockDim.x + threadIdx.x;
    if (i >= N * 32) return;
    int row = i >> 5, l = i & 31;
    float di = dinv[row];
    float c = di * di;
    size_t base = (size_t)row * 128 + l * 4;
    float4 v = *(const float4*)(x + base);
    float4 a = *(const float4*)(xa + base);
    a.x += v.x * c; a.y += v.y * c; a.z += v.z * c; a.w += v.w * c;
    *(float4*)(xa + base) = a;
}
__global__ void colstats_kernel(const float* __restrict__ h, float* __restrict__ sum,
                                float* __restrict__ sumsq, int N) {
    int c = threadIdx.x;
    int r0 = blockIdx.x * 256;
    int r1 = min(r0 + 256, N);
    float s = 0.f, s2 = 0.f;
    for (int r = r0; r < r1; r++) {
        float v = h[(size_t)r * 256 + c];
        s += v;
        s2 = fmaf(v, v, s2);
    }
    atomicAdd(&sum[c], s);
    atomicAdd(&sumsq[c], s2);
}
__global__ void bnfinal_kernel(const float* __restrict__ sum, const float* __restrict__ sumsq,
                               const float* __restrict__ gamma, const float* __restrict__ beta,
                               float* __restrict__ sc, float* __restrict__ sh, int N) {
    int c = threadIdx.x;
    float invN = 1.0f / (float)N;
    float mu = sum[c] * invN;
    float var = fmaxf(sumsq[c] * invN - mu * mu, 0.f);
    float scv = gamma[c] * rsqrtf(var + 1e-5f);
    sc[c] = scv;
    sh[c] = beta[c] - mu * scv;
}
__global__ void ln_kernel(const float* __restrict__ agg, const float* __restrict__ t,
                          const float* __restrict__ dinv, const float* __restrict__ b2,
                          const float* __restrict__ lng, const float* __restrict__ lnb,
                          float* __restrict__ out, int N) {
    int w = (blockIdx.x * blockDim.x + threadIdx.x) >> 5;
    int lane = threadIdx.x & 31;
    if (w >= N) return;
    float di = dinv[w];
    float c = di * di;
    size_t base = (size_t)w * 128 + lane * 4;
    float4 a = *(const float4*)(agg + base);
    float4 tv = *(const float4*)(t + base);
    float4 bb = *(const float4*)(b2 + lane * 4);
    float4 v;
    v.x = fmaf(tv.x, c, a.x) + bb.x;
    v.y = fmaf(tv.y, c, a.y) + bb.y;
    v.z = fmaf(tv.z, c, a.z) + bb.z;
    v.w = fmaf(tv.w, c, a.w) + bb.w;
    float s = v.x + v.y + v.z + v.w;
    #pragma unroll
    for (int off = 16; off; off >>= 1) s += __shfl_xor_sync(0xffffffffu, s, off);
    float mu = s * (1.0f / 128.0f);
    float dx = v.x - mu, dy = v.y - mu, dz = v.z - mu, dw = v.w - mu;
    float q = dx * dx + dy * dy + dz * dz + dw * dw;
    #pragma unroll
    for (int off = 16; off; off >>= 1) q += __shfl_xor_sync(0xffffffffu, q, off);
    float rs = rsqrtf(q * (1.0f / 128.0f) + 1e-5f);
    float4 g = *(const float4*)(lng + lane * 4);
    float4 bo = *(const float4*)(lnb + lane * 4);
    float4 o;
    o.x = fmaxf(fmaf(dx * rs, g.x, bo.x), 0.f);
    o.y = fmaxf(fmaf(dy * rs, g.y, bo.y), 0.f);
    o.z = fmaxf(fmaf(dz * rs, g.z, bo.z), 0.f);
    o.w = fmaxf(fmaf(dw * rs, g.w, bo.w), 0.f);
    *(float4*)(out + base) = o;
}
__global__ void decode_kernel(const float* __restrict__ z, const int* __restrict__ ia,
                              const int* __restrict__ ib,
                              const float* __restrict__ cutoff, float* __restrict__ out,
                              int EL, int writeRound) {
    int w = (blockIdx.x * blockDim.x + threadIdx.x) >> 5;
    int lane = threadIdx.x & 31;
    if (w >= EL) return;
    int a = ia[w];
    int b = ib[w];
    float4 za = *(const float4*)(z + (size_t)a * 128 + lane * 4);
    float4 zb = *(const float4*)(z + (size_t)b * 128 + lane * 4);
    float s = za.x * zb.x + za.y * zb.y + za.z * zb.z + za.w * zb.w;
    #pragma unroll
    for (int off = 16; off; off >>= 1) s += __shfl_xor_sync(0xffffffffu, s, off);
    if (lane == 0) {
        out[w] = s;
        if (writeRound) out[(size_t)EL + w] = (s < cutoff[0]) ? 0.0f : 1.0f;
    }
}

// ============================ pipelined mma.sync tf32x3 GEMM ============================
// C[128x128 tile] = op(A)[Nrows,K] @ BT^T, BT pre-split hi/lo [NOUT][K] K-major.
// FUSE: a' = relu(a*sc[k]+sh[k]).  8 warps 2(M)x4(N), warp tile 64x32,
// m16n8k8 tf32, 3-term hi/lo split.  A: register prefetch 1 chunk ahead.
// B: cp.async double-buffered 1 chunk ahead.
template<int K, bool FUSE, bool HASBIAS>
__global__ void __launch_bounds__(256, 2)
mm_gemm_kernel(const float* __restrict__ A,
               const float* __restrict__ BTh, const float* __restrict__ BTl,
               const float* __restrict__ bias,
               const float* __restrict__ sc, const float* __restrict__ sh,
               float* __restrict__ C, int Nrows, int ldC) {
    constexpr int NC  = K / 32;          // k-chunks of 32
    constexpr int PAD = 36;              // floats per padded row
    constexpr int ASZ = 128 * PAD * 4;   // 18432 B per copy
    // layout: [Ah][Al][buf0: Bh,Bl][buf1: Bh,Bl]  => 6*ASZ = 110592 B

    extern __shared__ char smem[];
    float* sAh = (float*)(smem);
    float* sAl = (float*)(smem + ASZ);

    int tid = threadIdx.x, lane = tid & 31, warp = tid >> 5;
    int warpM = warp & 1, warpN = warp >> 1;
    int rowBase  = blockIdx.x * 128;
    int colBaseG = blockIdx.y * 128;

    float acc[4][4][4];
    #pragma unroll
    for (int i = 0; i < 4; i++)
        #pragma unroll
        for (int j = 0; j < 4; j++)
            #pragma unroll
            for (int r = 0; r < 4; r++) acc[i][j][r] = 0.f;

    // loaders: each thread owns (row = tid/2, k-half = (tid&1)*16)
    int larow  = tid >> 1;
    int lkhalf = (tid & 1) * 16;
    bool rOK = (rowBase + larow) < Nrows;
    const float* aRow  = A   + (size_t)(rowBase + larow) * K + lkhalf;
    const float* bRowH = BTh + (size_t)(colBaseG + larow) * K + lkhalf;
    const float* bRowL = BTl + (size_t)(colBaseG + larow) * K + lkhalf;
    float* sAhp = sAh + larow * PAD + lkhalf;
    float* sAlp = sAl + larow * PAD + lkhalf;
    uint32_t sBdst = smem_u32(smem) + 2 * ASZ + (uint32_t)((larow * PAD + lkhalf) * 4);

    // ldmatrix per-lane addresses (row stride = PAD*4 = 144 B)
    int al_r = (lane & 7) + (lane & 8);
    int al_k = (lane & 16) >> 2;
    uint32_t aHbase = smem_u32(sAh) + (uint32_t)(((warpM * 64 + al_r) * PAD + al_k) << 2);
    uint32_t aLbase = aHbase + ASZ;
    int bl_n = (lane & 7) + ((lane & 16) >> 1);
    int bl_k = (lane & 8) >> 1;
    uint32_t bHbase0 = smem_u32(smem) + 2 * ASZ +
                       (uint32_t)(((warpN * 32 + bl_n) * PAD + bl_k) << 2);

    // ---- prologue: prefetch chunk 0
    float4 ar[4];
    {
        const float4* ap = (const float4*)(aRow);
        #pragma unroll
        for (int j = 0; j < 4; j++)
            ar[j] = rOK ? ap[j] : make_float4(0.f, 0.f, 0.f, 0.f);
        #pragma unroll
        for (int j = 0; j < 4; j++) CP_ASYNC16(sBdst + j * 16, bRowH + j * 4);
        #pragma unroll
        for (int j = 0; j < 4; j++) CP_ASYNC16(sBdst + ASZ + j * 16, bRowL + j * 4);
        CP_COMMIT();
    }

    for (int c = 0; c < NC; c++) {
        int b = c & 1;
        __syncthreads();   // previous chunk's mma reads of sA done
        // ---- store split A (chunk c) from regs
        #pragma unroll
        for (int j = 0; j < 4; j++) {
            float4 v = ar[j];
            if (FUSE) {
                int kg = c * 32 + lkhalf + j * 4;
                float4 s4 = *(const float4*)(sc + kg);
                float4 h4 = *(const float4*)(sh + kg);
                v.x = fmaxf(fmaf(v.x, s4.x, h4.x), 0.f);
                v.y = fmaxf(fmaf(v.y, s4.y, h4.y), 0.f);
                v.z = fmaxf(fmaf(v.z, s4.z, h4.z), 0.f);
                v.w = fmaxf(fmaf(v.w, s4.w, h4.w), 0.f);
            }
            float4 hi, lo;
            hi.x = tf32rnd(v.x); lo.x = tf32rnd(v.x - hi.x);
            hi.y = tf32rnd(v.y); lo.y = tf32rnd(v.y - hi.y);
            hi.z = tf32rnd(v.z); lo.z = tf32rnd(v.z - hi.z);
            hi.w = tf32rnd(v.w); lo.w = tf32rnd(v.w - hi.w);
            *(float4*)(sAhp + j * 4) = hi;
            *(float4*)(sAlp + j * 4) = lo;
        }
        // ---- prefetch chunk c+1 (A regs + B cp.async into other buffer)
        if (c + 1 < NC) {
            int k1 = (c + 1) * 32;
            const float4* ap = (const float4*)(aRow + k1);
            #pragma unroll
            for (int j = 0; j < 4; j++)
                ar[j] = rOK ? ap[j] : make_float4(0.f, 0.f, 0.f, 0.f);
            uint32_t dstB = sBdst + (uint32_t)((b ^ 1) * 2 * ASZ);
            #pragma unroll
            for (int j = 0; j < 4; j++) CP_ASYNC16(dstB + j * 16, bRowH + k1 + j * 4);
            #pragma unroll
            for (int j = 0; j < 4; j++) CP_ASYNC16(dstB + ASZ + j * 16, bRowL + k1 + j * 4);
            CP_COMMIT();
            CP_WAIT(1);   // chunk c's B group done
        } else {
            CP_WAIT(0);
        }
        __syncthreads();

        // ---- compute chunk c: 4 k8 steps
        uint32_t bHb = bHbase0 + (uint32_t)(b * 2 * ASZ);
        uint32_t bLb = bHb + ASZ;
        #pragma unroll
        for (int s = 0; s < 4; s++) {
            uint32_t koff = (uint32_t)(s * 8 * 4);
            uint32_t bh[2][4], bl[2][4];
            #pragma unroll
            for (int p = 0; p < 2; p++) {
                uint32_t po = (uint32_t)(p * 16 * PAD * 4);
                LDSM_X4(bh[p][0], bh[p][1], bh[p][2], bh[p][3], bHb + po + koff);
                LDSM_X4(bl[p][0], bl[p][1], bl[p][2], bl[p][3], bLb + po + koff);
            }
            #pragma unroll
            for (int i = 0; i < 4; i++) {
                uint32_t io = (uint32_t)(i * 16 * PAD * 4);
                uint32_t ah0, ah1, ah2, ah3, al0, al1, al2, al3;
                LDSM_X4(ah0, ah1, ah2, ah3, aHbase + io + koff);
                LDSM_X4(al0, al1, al2, al3, aLbase + io + koff);
                #pragma unroll
                for (int j = 0; j < 4; j++) {
                    int p = j >> 1, o = (j & 1) * 2;
                    MMA_TF32(acc[i][j], ah0, ah1, ah2, ah3, bh[p][o], bh[p][o + 1]);
                    MMA_TF32(acc[i][j], ah0, ah1, ah2, ah3, bl[p][o], bl[p][o + 1]);
                    MMA_TF32(acc[i][j], al0, al1, al2, al3, bh[p][o], bh[p][o + 1]);
                }
            }
        }
    }

    // ---- epilogue
    int gid = lane >> 2, tc2 = (lane & 3) * 2;
    #pragma unroll
    for (int i = 0; i < 4; i++) {
        int r0 = rowBase + warpM * 64 + i * 16 + gid;
        int r1 = r0 + 8;
        #pragma unroll
        for (int j = 0; j < 4; j++) {
            int col = colBaseG + warpN * 32 + j * 8 + tc2;
            float bx = 0.f, by = 0.f;
            if (HASBIAS) { bx = bias[col]; by = bias[col + 1]; }
            if (r0 < Nrows) {
                float2 v = make_float2(acc[i][j][0] + bx, acc[i][j][1] + by);
                *(float2*)(C + (size_t)r0 * ldC + col) = v;
            }
            if (r1 < Nrows) {
                float2 v = make_float2(acc[i][j][2] + bx, acc[i][j][3] + by);
                *(float2*)(C + (size_t)r1 * ldC + col) = v;
            }
        }
    }
}

// ============================ launch ============================
extern "C" void kernel_launch(void* const* d_in, const int* in_sizes, int n_in,
                              void* d_out, int out_size) {
    const float* x    = (const float*)d_in[0];
    const int*   ei   = (const int*)d_in[1];
    const int*   eli  = (const int*)d_in[2];
    const float* cut  = (const float*)d_in[3];
    const float* W1   = (const float*)d_in[4];
    const float* b1   = (const float*)d_in[5];
    const float* bng  = (const float*)d_in[6];
    const float* bnb  = (const float*)d_in[7];
    const float* W2   = (const float*)d_in[8];
    const float* b2   = (const float*)d_in[9];
    const float* lng  = (const float*)d_in[10];
    const float* lnb  = (const float*)d_in[11];
    const float* linW = (const float*)d_in[12];
    const float* linb = (const float*)d_in[13];

    int N  = in_sizes[0] / 128;
    int E  = in_sizes[1] / 2;
    int EL = in_sizes[2] / 2;
    const int* src = ei;
    const int* dst = ei + E;
    const int* la  = eli;
    const int* lb  = eli + EL;
    float* out = (float*)d_out;

    void* p;
    float *deg, *xa, *h1, *t, *h2, *z, *bsum, *bsq, *bsc, *bsh;
    float *w1h, *w1l, *w2h, *w2l, *w3h, *w3l;
    cudaGetSymbolAddress(&p, g_deg);     deg  = (float*)p;
    cudaGetSymbolAddress(&p, g_xa);      xa   = (float*)p;
    cudaGetSymbolAddress(&p, g_h1);      h1   = (float*)p;
    cudaGetSymbolAddress(&p, g_t);       t    = (float*)p;
    cudaGetSymbolAddress(&p, g_h2);      h2   = (float*)p;
    cudaGetSymbolAddress(&p, g_z);       z    = (float*)p;
    cudaGetSymbolAddress(&p, g_bnsum);   bsum = (float*)p;
    cudaGetSymbolAddress(&p, g_bnsumsq); bsq  = (float*)p;
    cudaGetSymbolAddress(&p, g_bnsc);    bsc  = (float*)p;
    cudaGetSymbolAddress(&p, g_bnsh);    bsh  = (float*)p;
    cudaGetSymbolAddress(&p, g_w1t_hi);  w1h  = (float*)p;
    cudaGetSymbolAddress(&p, g_w1t_lo);  w1l  = (float*)p;
    cudaGetSymbolAddress(&p, g_w2t_hi);  w2h  = (float*)p;
    cudaGetSymbolAddress(&p, g_w2t_lo);  w2l  = (float*)p;
    cudaGetSymbolAddress(&p, g_w3t_hi);  w3h  = (float*)p;
    cudaGetSymbolAddress(&p, g_w3t_lo);  w3l  = (float*)p;

    constexpr int SMEMSZ = 6 * 128 * 36 * 4;  // 110592 B
    cudaFuncSetAttribute(mm_gemm_kernel<128, false, true>,
                         cudaFuncAttributeMaxDynamicSharedMemorySize, SMEMSZ);
    cudaFuncSetAttribute(mm_gemm_kernel<256, true, false>,
                         cudaFuncAttributeMaxDynamicSharedMemorySize, SMEMSZ);

    cudaMemsetAsync(deg, 0, (size_t)N * sizeof(float));
    cudaMemsetAsync(xa,  0, (size_t)N * 128 * sizeof(float));
    cudaMemsetAsync(h2,  0, (size_t)N * 128 * sizeof(float));
    cudaMemsetAsync(bsum, 0, 256 * sizeof(float));
    cudaMemsetAsync(bsq,  0, 256 * sizeof(float));

    // pre-split weights (tiny)
    wsplit_kernel<<<(128 * 256 + 255) / 256, 256>>>(W1, w1h, w1l, 128, 256);
    wsplit_kernel<<<(256 * 128 + 255) / 256, 256>>>(W2, w2h, w2l, 256, 128);
    wsplit_kernel<<<(128 * 128 + 255) / 256, 256>>>(linW, w3h, w3l, 128, 128);

    // degree + dinv
    deg_kernel<<<(E + 255) / 256, 256>>>(deg, dst, E);
    dinv_kernel<<<(N + 255) / 256, 256>>>(deg, N);

    int tiles = (N + 127) / 128;

    // layer 1: aggregate x, then GEMM1 (+b1), NOUT=256 via 2 column tiles
    agg_kernel<<<(E + 7) / 8, 256>>>(x, xa, src, dst, E, deg);
    selfloop_kernel<<<((size_t)N * 32 + 255) / 256, 256>>>(x, deg, xa, N);
    mm_gemm_kernel<128, false, true><<<dim3(tiles, 2), 256, SMEMSZ>>>(
        xa, w1h, w1l, b1, nullptr, nullptr, h1, N, 256);

    // BatchNorm stats
    colstats_kernel<<<(N + 255) / 256, 256>>>(h1, bsum, bsq, N);
    bnfinal_kernel<<<1, 256>>>(bsum, bsq, bng, bnb, bsc, bsh, N);

    // layer 2: GEMM2 with fused BN+ReLU on A, then aggregate
    mm_gemm_kernel<256, true, false><<<dim3(tiles, 1), 256, SMEMSZ>>>(
        h1, w2h, w2l, nullptr, bsc, bsh, t, N, 128);
    agg_kernel<<<(E + 7) / 8, 256>>>(t, h2, src, dst, E, deg);

    // self-loop + bias + LayerNorm + ReLU -> xa
    ln_kernel<<<((size_t)N * 32 + 255) / 256, 256>>>(h2, t, deg, b2, lng, lnb, xa, N);

    // final linear (+linb)
    mm_gemm_kernel<128, false, true><<<dim3(tiles, 1), 256, SMEMSZ>>>(
        xa, w3h, w3l, linb, nullptr, nullptr, z, N, 128);

    // decode
    int writeRound = (out_size >= 2 * EL) ? 1 : 0;
    decode_kernel<<<((size_t)EL + 7) / 8, 256>>>(z, la, lb, cut, out, EL, writeRound);
}

// round 12
// speedup vs baseline: 1.5357x; 1.3474x over previous
#include <cuda_runtime.h>
#include <cuda_fp16.h>
#include <cstdint>

// ============================ helpers ============================
__device__ __forceinline__ float tf32rnd(float x) {
    uint32_t o; asm("cvt.rna.tf32.f32 %0, %1;" : "=r"(o) : "f"(x)); return __uint_as_float(o);
}
__device__ __forceinline__ uint32_t smem_u32(const void* p) {
    uint32_t a;
    asm("{ .reg .u64 t; cvta.to.shared.u64 t, %1; cvt.u32.u64 %0, t; }" : "=r"(a) : "l"(p));
    return a;
}
#define LDSM_X4(r0, r1, r2, r3, addr) \
    asm volatile("ldmatrix.sync.aligned.m8n8.x4.shared.b16 {%0,%1,%2,%3}, [%4];" \
                 : "=r"(r0), "=r"(r1), "=r"(r2), "=r"(r3) : "r"(addr))
#define MMA_TF32(d, a0, a1, a2, a3, b0, b1) \
    asm volatile("mma.sync.aligned.m16n8k8.row.col.f32.tf32.tf32.f32 " \
                 "{%0,%1,%2,%3},{%4,%5,%6,%7},{%8,%9},{%0,%1,%2,%3};" \
                 : "+f"(d[0]), "+f"(d[1]), "+f"(d[2]), "+f"(d[3]) \
                 : "r"(a0), "r"(a1), "r"(a2), "r"(a3), "r"(b0), "r"(b1))

// ============================ scratch ============================
#define MAXN 100000
#define MAXE 1000000
__device__ float g_dinv[MAXN];
__device__ int   g_cnt[MAXN];
__device__ int   g_rowstart[MAXN + 1];
__device__ int   g_cursor[MAXN];
__device__ int   g_blksum[1024];
__device__ int   g_csrsrc[MAXE];
__device__ float g_csrcoef[MAXE];
__device__ float g_xa[(size_t)MAXN * 128];
__device__ float g_h1[(size_t)MAXN * 256];
__device__ float g_t [(size_t)MAXN * 128];
__device__ float g_z [(size_t)MAXN * 128];
__device__ float g_bnsum[256];
__device__ float g_bnsumsq[256];
__device__ float g_bnsc[256];
__device__ float g_bnsh[256];
__device__ float g_w1t_hi[256 * 128];
__device__ float g_w1t_lo[256 * 128];
__device__ float g_w2t_hi[128 * 256];
__device__ float g_w2t_lo[128 * 256];
__device__ float g_w3t_hi[128 * 128];
__device__ float g_w3t_lo[128 * 128];

// ============================ CSR build ============================
__global__ void hist_kernel(int* __restrict__ cnt, const int* __restrict__ dst, int E) {
    int i = blockIdx.x * blockDim.x + threadIdx.x;
    if (i < E) atomicAdd(&cnt[dst[i]], 1);
}
__global__ void dinv_kernel(const int* __restrict__ cnt, float* __restrict__ dinv, int N) {
    int i = blockIdx.x * blockDim.x + threadIdx.x;
    if (i < N) dinv[i] = rsqrtf((float)cnt[i] + 1.0f);
}
// block-level exclusive scan (256 threads), writes block totals
__global__ void ps1_kernel(const int* __restrict__ cnt, int* __restrict__ excl,
                           int* __restrict__ blksum, int N) {
    __shared__ int wsum[8];
    int t = threadIdx.x;
    int i = blockIdx.x * 256 + t;
    int v = (i < N) ? cnt[i] : 0;
    int lane = t & 31, wid = t >> 5;
    int x = v;
    #pragma unroll
    for (int o = 1; o < 32; o <<= 1) {
        int y = __shfl_up_sync(0xffffffffu, x, o);
        if (lane >= o) x += y;
    }
    if (lane == 31) wsum[wid] = x;
    __syncthreads();
    if (t == 0) {
        int run = 0;
        #pragma unroll
        for (int w = 0; w < 8; w++) { int tmp = wsum[w]; wsum[w] = run; run += tmp; }
        blksum[blockIdx.x] = run;
    }
    __syncthreads();
    if (i < N) excl[i] = x - v + wsum[wid];
}
// scan block sums (nb <= 512), one block of 512
__global__ void ps2_kernel(int* __restrict__ blksum, int nb) {
    __shared__ int wsum[16];
    int t = threadIdx.x;
    int v = (t < nb) ? blksum[t] : 0;
    int lane = t & 31, wid = t >> 5;
    int x = v;
    #pragma unroll
    for (int o = 1; o < 32; o <<= 1) {
        int y = __shfl_up_sync(0xffffffffu, x, o);
        if (lane >= o) x += y;
    }
    if (lane == 31) wsum[wid] = x;
    __syncthreads();
    if (t == 0) {
        int run = 0;
        #pragma unroll
        for (int w = 0; w < 16; w++) { int tmp = wsum[w]; wsum[w] = run; run += tmp; }
    }
    __syncthreads();
    if (t < nb) blksum[t] = x - v + wsum[wid];
}
__global__ void ps3_kernel(int* __restrict__ excl, const int* __restrict__ blksum,
                           int* __restrict__ cursor, int N, int E) {
    int i = blockIdx.x * 256 + threadIdx.x;
    if (i < N) {
        int v = excl[i] + blksum[blockIdx.x];
        excl[i] = v;
        cursor[i] = v;
    }
    if (i == 0) excl[N] = E;
}
__global__ void scatter_kernel(const int* __restrict__ src, const int* __restrict__ dst,
                               int* __restrict__ cursor, int* __restrict__ csrc,
                               float* __restrict__ ccoef, const float* __restrict__ dinv, int E) {
    int e = blockIdx.x * blockDim.x + threadIdx.x;
    if (e >= E) return;
    int s = src[e], d = dst[e];
    int pos = atomicAdd(&cursor[d], 1);
    csrc[pos]  = s;
    ccoef[pos] = dinv[s] * dinv[d];
}

// ============================ fused CSR aggregation ============================
// warp per node: acc = sum_{edges} feat[s]*coef + feat[d]*dinv[d]^2  (self-loop)
// FLN: additionally + b2, LayerNorm(g,b), ReLU
template<bool FLN>
__global__ void agg_csr_kernel(const float* __restrict__ feat, float* __restrict__ out,
                               const int* __restrict__ rowstart, const int* __restrict__ csrc,
                               const float* __restrict__ ccoef, const float* __restrict__ dinv,
                               int N, const float* __restrict__ b2,
                               const float* __restrict__ lng, const float* __restrict__ lnb) {
    int w = (blockIdx.x * blockDim.x + threadIdx.x) >> 5;
    int lane = threadIdx.x & 31;
    if (w >= N) return;
    int beg = rowstart[w], end = rowstart[w + 1];
    float4 a0 = make_float4(0.f, 0.f, 0.f, 0.f);
    float4 a1 = make_float4(0.f, 0.f, 0.f, 0.f);
    int idx = beg;
    for (; idx + 1 < end; idx += 2) {
        int s0 = __ldg(&csrc[idx]), s1 = __ldg(&csrc[idx + 1]);
        float c0 = __ldg(&ccoef[idx]), c1 = __ldg(&ccoef[idx + 1]);
        float4 f0 = *(const float4*)(feat + (size_t)s0 * 128 + lane * 4);
        float4 f1 = *(const float4*)(feat + (size_t)s1 * 128 + lane * 4);
        a0.x = fmaf(f0.x, c0, a0.x); a0.y = fmaf(f0.y, c0, a0.y);
        a0.z = fmaf(f0.z, c0, a0.z); a0.w = fmaf(f0.w, c0, a0.w);
        a1.x = fmaf(f1.x, c1, a1.x); a1.y = fmaf(f1.y, c1, a1.y);
        a1.z = fmaf(f1.z, c1, a1.z); a1.w = fmaf(f1.w, c1, a1.w);
    }
    if (idx < end) {
        int s0 = __ldg(&csrc[idx]);
        float c0 = __ldg(&ccoef[idx]);
        float4 f0 = *(const float4*)(feat + (size_t)s0 * 128 + lane * 4);
        a0.x = fmaf(f0.x, c0, a0.x); a0.y = fmaf(f0.y, c0, a0.y);
        a0.z = fmaf(f0.z, c0, a0.z); a0.w = fmaf(f0.w, c0, a0.w);
    }
    float di = dinv[w];
    float c2 = di * di;
    float4 fs = *(const float4*)(feat + (size_t)w * 128 + lane * 4);
    float4 v;
    v.x = fmaf(fs.x, c2, a0.x + a1.x);
    v.y = fmaf(fs.y, c2, a0.y + a1.y);
    v.z = fmaf(fs.z, c2, a0.z + a1.z);
    v.w = fmaf(fs.w, c2, a0.w + a1.w);
    size_t base = (size_t)w * 128 + lane * 4;
    if (!FLN) {
        *(float4*)(out + base) = v;
        return;
    }
    float4 bb = *(const float4*)(b2 + lane * 4);
    v.x += bb.x; v.y += bb.y; v.z += bb.z; v.w += bb.w;
    float s = v.x + v.y + v.z + v.w;
    #pragma unroll
    for (int off = 16; off; off >>= 1) s += __shfl_xor_sync(0xffffffffu, s, off);
    float mu = s * (1.0f / 128.0f);
    float dx = v.x - mu, dy = v.y - mu, dz = v.z - mu, dw = v.w - mu;
    float q = dx * dx + dy * dy + dz * dz + dw * dw;
    #pragma unroll
    for (int off = 16; off; off >>= 1) q += __shfl_xor_sync(0xffffffffu, q, off);
    float rs = rsqrtf(q * (1.0f / 128.0f) + 1e-5f);
    float4 g = *(const float4*)(lng + lane * 4);
    float4 bo = *(const float4*)(lnb + lane * 4);
    float4 o;
    o.x = fmaxf(fmaf(dx * rs, g.x, bo.x), 0.f);
    o.y = fmaxf(fmaf(dy * rs, g.y, bo.y), 0.f);
    o.z = fmaxf(fmaf(dz * rs, g.z, bo.z), 0.f);
    o.w = fmaxf(fmaf(dw * rs, g.w, bo.w), 0.f);
    *(float4*)(out + base) = o;
}

// ============================ misc kernels ============================
__global__ void wsplit_kernel(const float* __restrict__ W, float* __restrict__ hiT,
                              float* __restrict__ loT, int K, int NOUT) {
    int i = blockIdx.x * blockDim.x + threadIdx.x;
    if (i >= K * NOUT) return;
    int k = i / NOUT, n = i % NOUT;
    float x = W[i];
    float h = tf32rnd(x);
    float l = tf32rnd(x - h);
    hiT[(size_t)n * K + k] = h;
    loT[(size_t)n * K + k] = l;
}
__global__ void colstats_kernel(const float* __restrict__ h, float* __restrict__ sum,
                                float* __restrict__ sumsq, int N) {
    int c = threadIdx.x;
    int r0 = blockIdx.x * 256;
    int r1 = min(r0 + 256, N);
    float s = 0.f, s2 = 0.f;
    for (int r = r0; r < r1; r++) {
        float v = h[(size_t)r * 256 + c];
        s += v;
        s2 = fmaf(v, v, s2);
    }
    atomicAdd(&sum[c], s);
    atomicAdd(&sumsq[c], s2);
}
__global__ void bnfinal_kernel(const float* __restrict__ sum, const float* __restrict__ sumsq,
                               const float* __restrict__ gamma, const float* __restrict__ beta,
                               float* __restrict__ sc, float* __restrict__ sh, int N) {
    int c = threadIdx.x;
    float invN = 1.0f / (float)N;
    float mu = sum[c] * invN;
    float var = fmaxf(sumsq[c] * invN - mu * mu, 0.f);
    float scv = gamma[c] * rsqrtf(var + 1e-5f);
    sc[c] = scv;
    sh[c] = beta[c] - mu * scv;
}
__global__ void decode_kernel(const float* __restrict__ z, const int* __restrict__ ia,
                              const int* __restrict__ ib,
                              const float* __restrict__ cutoff, float* __restrict__ out,
                              int EL, int writeRound) {
    int w = (blockIdx.x * blockDim.x + threadIdx.x) >> 5;
    int lane = threadIdx.x & 31;
    if (w >= EL) return;
    int a = ia[w];
    int b = ib[w];
    float4 za = *(const float4*)(z + (size_t)a * 128 + lane * 4);
    float4 zb = *(const float4*)(z + (size_t)b * 128 + lane * 4);
    float s = za.x * zb.x + za.y * zb.y + za.z * zb.z + za.w * zb.w;
    #pragma unroll
    for (int off = 16; off; off >>= 1) s += __shfl_xor_sync(0xffffffffu, s, off);
    if (lane == 0) {
        out[w] = s;
        if (writeRound) out[(size_t)EL + w] = (s < cutoff[0]) ? 0.0f : 1.0f;
    }
}

// ============================ mma.sync tf32x3 GEMM (R6 config) ============================
template<int K, bool FUSE, bool HASBIAS>
__global__ void __launch_bounds__(256, 2)
mm_gemm_kernel(const float* __restrict__ A,
               const float* __restrict__ BTh, const float* __restrict__ BTl,
               const float* __restrict__ bias,
               const float* __restrict__ sc, const float* __restrict__ sh,
               float* __restrict__ C, int Nrows, int ldC) {
    constexpr int NC  = K / 32;
    constexpr int PAD = 36;
    constexpr int ASZ = 128 * PAD * 4;

    extern __shared__ char smem[];
    float* sAh = (float*)(smem);
    float* sAl = (float*)(smem + ASZ);
    float* sBh = (float*)(smem + 2 * ASZ);
    float* sBl = (float*)(smem + 3 * ASZ);

    int tid = threadIdx.x, lane = tid & 31, warp = tid >> 5;
    int warpM = warp & 1, warpN = warp >> 1;
    int rowBase  = blockIdx.x * 128;
    int colBaseG = blockIdx.y * 128;

    float acc[4][4][4];
    #pragma unroll
    for (int i = 0; i < 4; i++)
        #pragma unroll
        for (int j = 0; j < 4; j++)
            #pragma unroll
            for (int r = 0; r < 4; r++) acc[i][j][r] = 0.f;

    int larow  = tid >> 1;
    int lkhalf = (tid & 1) * 16;
    bool rOK = (rowBase + larow) < Nrows;
    const float* aRow  = A   + (size_t)(rowBase + larow) * K + lkhalf;
    const float* bRowH = BTh + (size_t)(colBaseG + larow) * K + lkhalf;
    const float* bRowL = BTl + (size_t)(colBaseG + larow) * K + lkhalf;
    float* sAhp = sAh + larow * PAD + lkhalf;
    float* sAlp = sAl + larow * PAD + lkhalf;
    float* sBhp = sBh + larow * PAD + lkhalf;
    float* sBlp = sBl + larow * PAD + lkhalf;

    int al_r = (lane & 7) + (lane & 8);
    int al_k = (lane & 16) >> 2;
    uint32_t aHbase = smem_u32(sAh) + (uint32_t)(((warpM * 64 + al_r) * PAD + al_k) << 2);
    uint32_t aLbase = aHbase + ASZ;
    int bl_n = (lane & 7) + ((lane & 16) >> 1);
    int bl_k = (lane & 8) >> 1;
    uint32_t bHbase = smem_u32(sBh) + (uint32_t)(((warpN * 32 + bl_n) * PAD + bl_k) << 2);
    uint32_t bLbase = bHbase + ASZ;

    for (int c = 0; c < NC; c++) {
        int k0 = c * 32;
        __syncthreads();
        {
            const float4* ap = (const float4*)(aRow + k0);
            #pragma unroll
            for (int j = 0; j < 4; j++) {
                float4 v = rOK ? ap[j] : make_float4(0.f, 0.f, 0.f, 0.f);
                if (FUSE) {
                    int kg = k0 + lkhalf + j * 4;
                    float4 s4 = *(const float4*)(sc + kg);
                    float4 h4 = *(const float4*)(sh + kg);
                    v.x = fmaxf(fmaf(v.x, s4.x, h4.x), 0.f);
                    v.y = fmaxf(fmaf(v.y, s4.y, h4.y), 0.f);
                    v.z = fmaxf(fmaf(v.z, s4.z, h4.z), 0.f);
                    v.w = fmaxf(fmaf(v.w, s4.w, h4.w), 0.f);
                }
                float4 hi, lo;
                hi.x = tf32rnd(v.x); lo.x = tf32rnd(v.x - hi.x);
                hi.y = tf32rnd(v.y); lo.y = tf32rnd(v.y - hi.y);
                hi.z = tf32rnd(v.z); lo.z = tf32rnd(v.z - hi.z);
                hi.w = tf32rnd(v.w); lo.w = tf32rnd(v.w - hi.w);
                *(float4*)(sAhp + j * 4) = hi;
                *(float4*)(sAlp + j * 4) = lo;
            }
        }
        {
            const float4* bh = (const float4*)(bRowH + k0);
            const float4* bl = (const float4*)(bRowL + k0);
            #pragma unroll
            for (int j = 0; j < 4; j++) *(float4*)(sBhp + j * 4) = bh[j];
            #pragma unroll
            for (int j = 0; j < 4; j++) *(float4*)(sBlp + j * 4) = bl[j];
        }
        __syncthreads();

        #pragma unroll
        for (int s = 0; s < 4; s++) {
            uint32_t koff = (uint32_t)(s * 8 * 4);
            uint32_t bh[2][4], bl[2][4];
            #pragma unroll
            for (int p = 0; p < 2; p++) {
                uint32_t po = (uint32_t)(p * 16 * PAD * 4);
                LDSM_X4(bh[p][0], bh[p][1], bh[p][2], bh[p][3], bHbase + po + koff);
                LDSM_X4(bl[p][0], bl[p][1], bl[p][2], bl[p][3], bLbase + po + koff);
            }
            #pragma unroll
            for (int i = 0; i < 4; i++) {
                uint32_t io = (uint32_t)(i * 16 * PAD * 4);
                uint32_t ah0, ah1, ah2, ah3, alo0, alo1, alo2, alo3;
                LDSM_X4(ah0, ah1, ah2, ah3, aHbase + io + koff);
                LDSM_X4(alo0, alo1, alo2, alo3, aLbase + io + koff);
                #pragma unroll
                for (int j = 0; j < 4; j++) {
                    int p = j >> 1, o = (j & 1) * 2;
                    MMA_TF32(acc[i][j], ah0, ah1, ah2, ah3, bh[p][o], bh[p][o + 1]);
                    MMA_TF32(acc[i][j], ah0, ah1, ah2, ah3, bl[p][o], bl[p][o + 1]);
                    MMA_TF32(acc[i][j], alo0, alo1, alo2, alo3, bh[p][o], bh[p][o + 1]);
                }
            }
        }
    }

    int gid = lane >> 2, tc2 = (lane & 3) * 2;
    #pragma unroll
    for (int i = 0; i < 4; i++) {
        int r0 = rowBase + warpM * 64 + i * 16 + gid;
        int r1 = r0 + 8;
        #pragma unroll
        for (int j = 0; j < 4; j++) {
            int col = colBaseG + warpN * 32 + j * 8 + tc2;
            float bx = 0.f, by = 0.f;
            if (HASBIAS) { bx = bias[col]; by = bias[col + 1]; }
            if (r0 < Nrows) {
                float2 v = make_float2(acc[i][j][0] + bx, acc[i][j][1] + by);
                *(float2*)(C + (size_t)r0 * ldC + col) = v;
            }
            if (r1 < Nrows) {
                float2 v = make_float2(acc[i][j][2] + bx, acc[i][j][3] + by);
                *(float2*)(C + (size_t)r1 * ldC + col) = v;
            }
        }
    }
}

// ============================ launch ============================
extern "C" void kernel_launch(void* const* d_in, const int* in_sizes, int n_in,
                              void* d_out, int out_size) {
    const float* x    = (const float*)d_in[0];
    const int*   ei   = (const int*)d_in[1];
    const int*   eli  = (const int*)d_in[2];
    const float* cut  = (const float*)d_in[3];
    const float* W1   = (const float*)d_in[4];
    const float* b1   = (const float*)d_in[5];
    const float* bng  = (const float*)d_in[6];
    const float* bnb  = (const float*)d_in[7];
    const float* W2   = (const float*)d_in[8];
    const float* b2   = (const float*)d_in[9];
    const float* lng  = (const float*)d_in[10];
    const float* lnb  = (const float*)d_in[11];
    const float* linW = (const float*)d_in[12];
    const float* linb = (const float*)d_in[13];

    int N  = in_sizes[0] / 128;
    int E  = in_sizes[1] / 2;
    int EL = in_sizes[2] / 2;
    const int* src = ei;
    const int* dst = ei + E;
    const int* la  = eli;
    const int* lb  = eli + EL;
    float* out = (float*)d_out;

    void* p;
    float *dinv, *xa, *h1, *t, *z, *bsum, *bsq, *bsc, *bsh, *ccoef;
    float *w1h, *w1l, *w2h, *w2l, *w3h, *w3l;
    int *cnt, *rowstart, *cursor, *blksum, *csrc;
    cudaGetSymbolAddress(&p, g_dinv);     dinv = (float*)p;
    cudaGetSymbolAddress(&p, g_cnt);      cnt  = (int*)p;
    cudaGetSymbolAddress(&p, g_rowstart); rowstart = (int*)p;
    cudaGetSymbolAddress(&p, g_cursor);   cursor = (int*)p;
    cudaGetSymbolAddress(&p, g_blksum);   blksum = (int*)p;
    cudaGetSymbolAddress(&p, g_csrsrc);   csrc  = (int*)p;
    cudaGetSymbolAddress(&p, g_csrcoef);  ccoef = (float*)p;
    cudaGetSymbolAddress(&p, g_xa);       xa   = (float*)p;
    cudaGetSymbolAddress(&p, g_h1);       h1   = (float*)p;
    cudaGetSymbolAddress(&p, g_t);        t    = (float*)p;
    cudaGetSymbolAddress(&p, g_z);        z    = (float*)p;
    cudaGetSymbolAddress(&p, g_bnsum);    bsum = (float*)p;
    cudaGetSymbolAddress(&p, g_bnsumsq);  bsq  = (float*)p;
    cudaGetSymbolAddress(&p, g_bnsc);     bsc  = (float*)p;
    cudaGetSymbolAddress(&p, g_bnsh);     bsh  = (float*)p;
    cudaGetSymbolAddress(&p, g_w1t_hi);   w1h  = (float*)p;
    cudaGetSymbolAddress(&p, g_w1t_lo);   w1l  = (float*)p;
    cudaGetSymbolAddress(&p, g_w2t_hi);   w2h  = (float*)p;
    cudaGetSymbolAddress(&p, g_w2t_lo);   w2l  = (float*)p;
    cudaGetSymbolAddress(&p, g_w3t_hi);   w3h  = (float*)p;
    cudaGetSymbolAddress(&p, g_w3t_lo);   w3l  = (float*)p;

    constexpr int SMEMSZ = 4 * 128 * 36 * 4;  // 73728 B (R6 config)
    cudaFuncSetAttribute(mm_gemm_kernel<128, false, true>,
                         cudaFuncAttributeMaxDynamicSharedMemorySize, SMEMSZ);
    cudaFuncSetAttribute(mm_gemm_kernel<256, true, false>,
                         cudaFuncAttributeMaxDynamicSharedMemorySize, SMEMSZ);

    cudaMemsetAsync(cnt,  0, (size_t)N * sizeof(int));
    cudaMemsetAsync(bsum, 0, 256 * sizeof(float));
    cudaMemsetAsync(bsq,  0, 256 * sizeof(float));

    // pre-split weights (tiny, independent)
    wsplit_kernel<<<(128 * 256 + 255) / 256, 256>>>(W1, w1h, w1l, 128, 256);
    wsplit_kernel<<<(256 * 128 + 255) / 256, 256>>>(W2, w2h, w2l, 256, 128);
    wsplit_kernel<<<(128 * 128 + 255) / 256, 256>>>(linW, w3h, w3l, 128, 128);

    // ---- CSR build
    int nb = (N + 255) / 256;
    hist_kernel<<<(E + 255) / 256, 256>>>(cnt, dst, E);
    dinv_kernel<<<nb, 256>>>(cnt, dinv, N);
    ps1_kernel<<<nb, 256>>>(cnt, rowstart, blksum, N);
    ps2_kernel<<<1, 512>>>(blksum, nb);
    ps3_kernel<<<nb, 256>>>(rowstart, blksum, cursor, N, E);
    scatter_kernel<<<(E + 255) / 256, 256>>>(src, dst, cursor, csrc, ccoef, dinv, E);

    int tiles = (N + 127) / 128;
    int aggblocks = (N + 7) / 8;

    // layer 1: CSR aggregate (incl self-loop) -> xa, GEMM1 (+b1)
    agg_csr_kernel<false><<<aggblocks, 256>>>(x, xa, rowstart, csrc, ccoef, dinv, N,
                                              nullptr, nullptr, nullptr);
    mm_gemm_kernel<128, false, true><<<dim3(tiles, 2), 256, SMEMSZ>>>(
        xa, w1h, w1l, b1, nullptr, nullptr, h1, N, 256);

    // BatchNorm stats
    colstats_kernel<<<(N + 255) / 256, 256>>>(h1, bsum, bsq, N);
    bnfinal_kernel<<<1, 256>>>(bsum, bsq, bng, bnb, bsc, bsh, N);

    // layer 2: GEMM2 (fused BN+ReLU on A) -> t, then CSR aggregate + b2 + LN + ReLU -> xa
    mm_gemm_kernel<256, true, false><<<dim3(tiles, 1), 256, SMEMSZ>>>(
        h1, w2h, w2l, nullptr, bsc, bsh, t, N, 128);
    agg_csr_kernel<true><<<aggblocks, 256>>>(t, xa, rowstart, csrc, ccoef, dinv, N,
                                             b2, lng, lnb);

    // final linear (+linb)
    mm_gemm_kernel<128, false, true><<<dim3(tiles, 1), 256, SMEMSZ>>>(
        xa, w3h, w3l, linb, nullptr, nullptr, z, N, 128);

    // decode
    int writeRound = (out_size >= 2 * EL) ? 1 : 0;
    decode_kernel<<<((size_t)EL + 7) / 8, 256>>>(z, la, lb, cut, out, EL, writeRound);
}